// round 1
// baseline (speedup 1.0000x reference)
#include <cuda_runtime.h>
#include <math.h>

// ---------------- scratch (no allocations allowed -> __device__ globals) ---
__device__ float g_u1[32ull * 24 * 256 * 256];   // 201 MB
__device__ float g_s1[32ull * 27 * 256 * 256];   // 226 MB
__device__ float g_u2[32ull * 216 * 128 * 128];  // 453 MB

// ---------------- band-pass + modulus kernel (stages 1 and 2) -------------
// For group g, effective channel c_eff = g % 3 selects phi[c_eff] and
// psi_{r,i}[c_eff*8 + p]  (because (g*8+p) % 24 == (g%3)*8 + p).
// Computes, per (b, g):  phi conv (stride 2)  -> phi_out channel g
//                        |psi conv| (stride 2)-> mod_out channels g*8+p
#define TBX 32
#define TBY 16
#define BSW (2*TBX + 5)   // 69
#define BSH (2*TBY + 5)   // 37

__global__ __launch_bounds__(256) void band_kernel(
    const float* __restrict__ in,     // [B*G, HIN, WIN]
    const float* __restrict__ phi,    // [3, 49]
    const float* __restrict__ psi_r,  // [24, 49]
    const float* __restrict__ psi_i,  // [24, 49]
    float* __restrict__ phi_out,      // [B, PHI_C, HOUT, WOUT]
    float* __restrict__ mod_out,      // [B, G*8, HOUT, WOUT]
    int HIN, int WIN, int HOUT, int WOUT,
    int G, int PHI_C)
{
    __shared__ float tile[BSH * BSW];
    __shared__ float wsm[49 * 17];

    const int tid = threadIdx.x;
    const int bz  = blockIdx.z;        // b*G + g
    const int b   = bz / G;
    const int g   = bz - b * G;
    const int c_eff = g % 3;

    // load the 17-filter bank for this group into smem: wsm[tap*17 + f]
    for (int idx = tid; idx < 49 * 17; idx += 256) {
        int t = idx / 17, f = idx - t * 17;
        float w;
        if (f == 0)     w = phi[c_eff * 49 + t];
        else if (f < 9) w = psi_r[(c_eff * 8 + (f - 1)) * 49 + t];
        else            w = psi_i[(c_eff * 8 + (f - 9)) * 49 + t];
        wsm[idx] = w;
    }

    const int ox0 = blockIdx.x * TBX;
    const int oy0 = blockIdx.y * TBY;
    const int iy0 = oy0 * 2 - 3;
    const int ix0 = ox0 * 2 - 3;
    const float* inp = in + (size_t)bz * HIN * WIN;

    // load input tile (zero pad at borders)
    for (int idx = tid; idx < BSH * BSW; idx += 256) {
        int r = idx / BSW, c = idx - r * BSW;
        int iy = iy0 + r, ix = ix0 + c;
        float v = 0.f;
        if ((unsigned)iy < (unsigned)HIN && (unsigned)ix < (unsigned)WIN)
            v = inp[iy * WIN + ix];
        tile[idx] = v;
    }
    __syncthreads();

    const int tx = tid & 31;        // 0..31 -> output x
    const int ty = tid >> 5;        // 0..7  -> output rows ty and ty+8

    float acc0[17], acc1[17];
    #pragma unroll
    for (int f = 0; f < 17; f++) { acc0[f] = 0.f; acc1[f] = 0.f; }

    const float* t0 = &tile[(2 * ty) * BSW + 2 * tx];
    const float* t1 = &tile[(2 * ty + 16) * BSW + 2 * tx];

    #pragma unroll 1
    for (int ky = 0; ky < 7; ky++) {
        #pragma unroll 1
        for (int kx = 0; kx < 7; kx++) {
            float v0 = t0[ky * BSW + kx];
            float v1 = t1[ky * BSW + kx];
            const float* w = &wsm[(ky * 7 + kx) * 17];
            #pragma unroll
            for (int f = 0; f < 17; f++) {
                float wv = w[f];
                acc0[f] = fmaf(v0, wv, acc0[f]);
                acc1[f] = fmaf(v1, wv, acc1[f]);
            }
        }
    }

    const int HW   = HOUT * WOUT;
    const int oy_a = oy0 + ty;
    const int oy_b = oy0 + ty + 8;
    const int ox   = ox0 + tx;

    float* po = phi_out + ((size_t)b * PHI_C + g) * HW;
    po[oy_a * WOUT + ox] = acc0[0];
    po[oy_b * WOUT + ox] = acc1[0];

    float* mo = mod_out + ((size_t)(b * G + g) * 8) * HW;
    #pragma unroll
    for (int p = 0; p < 8; p++) {
        float m0 = sqrtf(fmaf(acc0[1 + p], acc0[1 + p], acc0[9 + p] * acc0[9 + p]));
        float m1 = sqrtf(fmaf(acc1[1 + p], acc1[1 + p], acc1[9 + p] * acc1[9 + p]));
        mo[(size_t)p * HW + oy_a * WOUT + ox] = m0;
        mo[(size_t)p * HW + oy_b * WOUT + ox] = m1;
    }
}

// ---------------- depthwise stride-1 smoothing with phi[k%3] --------------
// Register-blocked: each thread computes an 8-row column -> FMA-bound
// (per tap group: 21 LDS vs 56 FFMA) instead of LDS-bound naive form.
#define TSX 32
#define TSY 64
#define SSW (TSX + 6)   // 38
#define SSH (TSY + 6)   // 70

__global__ __launch_bounds__(256) void smooth_kernel(
    const float* __restrict__ in,   // [B*CIN, H, W]
    const float* __restrict__ phi,  // [3, 49]
    float* __restrict__ out,        // [B, OUTC, H, W]
    int H, int W, int CIN, int OUTC, int OUTOFF)
{
    __shared__ float tile[SSH * SSW];
    __shared__ float wsm[49];

    const int tid = threadIdx.x;
    const int bz  = blockIdx.z;      // b*CIN + k
    const int b   = bz / CIN;
    const int k   = bz - b * CIN;
    const int c_eff = k % 3;

    if (tid < 49) wsm[tid] = phi[c_eff * 49 + tid];

    const int x0 = blockIdx.x * TSX;
    const int y0 = blockIdx.y * TSY;
    const float* inp = in + (size_t)bz * H * W;

    for (int idx = tid; idx < SSH * SSW; idx += 256) {
        int r = idx / SSW, c = idx - r * SSW;
        int iy = y0 - 3 + r, ix = x0 - 3 + c;
        float v = 0.f;
        if ((unsigned)iy < (unsigned)H && (unsigned)ix < (unsigned)W)
            v = inp[iy * W + ix];
        tile[idx] = v;
    }
    __syncthreads();

    const int tx  = tid & 31;
    const int yc  = tid >> 5;        // 0..7 -> 8-row chunk
    const int ry0 = yc * 8;

    float acc[8];
    #pragma unroll
    for (int o = 0; o < 8; o++) acc[o] = 0.f;

    #pragma unroll 1
    for (int kx = 0; kx < 7; kx++) {
        float v[14];
        #pragma unroll
        for (int i = 0; i < 14; i++)
            v[i] = tile[(ry0 + i) * SSW + tx + kx];
        #pragma unroll
        for (int ky = 0; ky < 7; ky++) {
            float wv = wsm[ky * 7 + kx];
            #pragma unroll
            for (int o = 0; o < 8; o++)
                acc[o] = fmaf(v[ky + o], wv, acc[o]);
        }
    }

    float* po = out + ((size_t)b * OUTC + OUTOFF + k) * H * W;
    #pragma unroll
    for (int o = 0; o < 8; o++)
        po[(y0 + ry0 + o) * W + x0 + tx] = acc[o];
}

// ---------------- launcher -------------------------------------------------
extern "C" void kernel_launch(void* const* d_in, const int* in_sizes, int n_in,
                              void* d_out, int out_size)
{
    const float* x     = (const float*)d_in[0];
    const float* phi   = (const float*)d_in[1];
    const float* psi_r = (const float*)d_in[2];
    const float* psi_i = (const float*)d_in[3];
    float* out = (float*)d_out;

    float *u1, *s1, *u2;
    cudaGetSymbolAddress((void**)&u1, g_u1);
    cudaGetSymbolAddress((void**)&s1, g_s1);
    cudaGetSymbolAddress((void**)&u2, g_u2);

    // Stage 1: x [32,3,512,512] -> s0_phi into s1 ch 0-2, |U1| into u1 [32,24,256,256]
    band_kernel<<<dim3(256 / TBX, 256 / TBY, 32 * 3), 256>>>(
        x, phi, psi_r, psi_i, s1, u1, 512, 512, 256, 256, 3, 27);

    // u1_smooth (depthwise stride 1, phi[k%3]) -> s1 ch 3-26
    smooth_kernel<<<dim3(256 / TSX, 256 / TSY, 32 * 24), 256>>>(
        u1, phi, s1, 256, 256, 24, 27, 3);

    // Stage 2: s1 [32,27,256,256] -> s1_phi into out ch 0-26, |U2| into u2 [32,216,128,128]
    band_kernel<<<dim3(128 / TBX, 128 / TBY, 32 * 27), 256>>>(
        s1, phi, psi_r, psi_i, out, u2, 256, 256, 128, 128, 27, 243);

    // u2_smooth -> out ch 27-242
    smooth_kernel<<<dim3(128 / TSX, 128 / TSY, 32 * 216), 256>>>(
        u2, phi, out, 128, 128, 216, 243, 27);
}